// round 6
// baseline (speedup 1.0000x reference)
#include <cuda_runtime.h>
#include <math.h>

typedef unsigned long long u64;

#define SPLITK 8

// Split-K partial sums of x @ W^T (bias added in circuit kernel). No allocs.
__device__ float g_com4[SPLITK][1024 * 512];

// ---------------------------------------------------------------------------
// Packed fp32x2 helpers (PTX-only)
// ---------------------------------------------------------------------------
__device__ __forceinline__ u64 pk2(float lo, float hi) {
    u64 d; asm("mov.b64 %0, {%1, %2};" : "=l"(d) : "f"(lo), "f"(hi)); return d;
}
__device__ __forceinline__ u64 fma2(u64 a, u64 b, u64 c) {
    u64 d; asm("fma.rn.f32x2 %0, %1, %2, %3;" : "=l"(d) : "l"(a), "l"(b), "l"(c)); return d;
}
__device__ __forceinline__ u64 mul2(u64 a, u64 b) {
    u64 d; asm("mul.rn.f32x2 %0, %1, %2;" : "=l"(d) : "l"(a), "l"(b)); return d;
}
__device__ __forceinline__ u64 add2(u64 a, u64 b) {
    u64 d; asm("add.rn.f32x2 %0, %1, %2;" : "=l"(d) : "l"(a), "l"(b)); return d;
}
__device__ __forceinline__ void unpk2(float& lo, float& hi, u64 d) {
    asm("mov.b64 {%0, %1}, %2;" : "=f"(lo), "=f"(hi) : "l"(d));
}
// swap halves: (x, y) -> (y, x)   (negation folded into coefficients)
__device__ __forceinline__ u64 hswap(u64 a) {
    float lo, hi; unpk2(lo, hi, a);
    return pk2(hi, lo);
}

// ---------------------------------------------------------------------------
// GEMM: split-K partials of x @ W^T.  SPLITK=8 -> 256 CTAs (full chip).
// BM=BN=128, BK=16, 256 threads, 8x8 per thread, f32x2 accumulators.
// ---------------------------------------------------------------------------
__global__ __launch_bounds__(256)
void gemm_v2(const float* __restrict__ A, const float* __restrict__ Wm)
{
    __shared__ __align__(16) float As[2][16][132];
    __shared__ __align__(16) float Ws[2][16][132];

    const int tid = threadIdx.x;
    const int n0 = blockIdx.x * 128;
    const int m0 = blockIdx.y * 128;
    const int kb = blockIdx.z * 256;        // 256 K per CTA -> 16 iters
    const int r  = tid >> 1;
    const int kh = (tid & 1) << 3;
    const int ty = tid >> 4;
    const int tx = tid & 15;

    const float* Ap = A  + (size_t)(m0 + r) * 2048 + kb + kh;
    const float* Wp = Wm + (size_t)(n0 + r) * 2048 + kb + kh;

    u64 acc[8][4];
    #pragma unroll
    for (int i = 0; i < 8; ++i)
        #pragma unroll
        for (int j = 0; j < 4; ++j) acc[i][j] = 0ull;

    float4 a0 = *(const float4*)Ap;
    float4 a1 = *(const float4*)(Ap + 4);
    float4 w0 = *(const float4*)Wp;
    float4 w1 = *(const float4*)(Wp + 4);

    #pragma unroll 1
    for (int it = 0; it < 16; ++it) {
        const int buf = it & 1;
        As[buf][kh + 0][r] = a0.x; As[buf][kh + 1][r] = a0.y;
        As[buf][kh + 2][r] = a0.z; As[buf][kh + 3][r] = a0.w;
        As[buf][kh + 4][r] = a1.x; As[buf][kh + 5][r] = a1.y;
        As[buf][kh + 6][r] = a1.z; As[buf][kh + 7][r] = a1.w;
        Ws[buf][kh + 0][r] = w0.x; Ws[buf][kh + 1][r] = w0.y;
        Ws[buf][kh + 2][r] = w0.z; Ws[buf][kh + 3][r] = w0.w;
        Ws[buf][kh + 4][r] = w1.x; Ws[buf][kh + 5][r] = w1.y;
        Ws[buf][kh + 6][r] = w1.z; Ws[buf][kh + 7][r] = w1.w;

        if (it + 1 < 16) {
            const float* Ap2 = Ap + (it + 1) * 16;
            const float* Wp2 = Wp + (it + 1) * 16;
            a0 = *(const float4*)Ap2; a1 = *(const float4*)(Ap2 + 4);
            w0 = *(const float4*)Wp2; w1 = *(const float4*)(Wp2 + 4);
        }
        __syncthreads();

        #pragma unroll
        for (int kk = 0; kk < 16; ++kk) {
            float4 af0 = *(const float4*)&As[buf][kk][ty << 3];
            float4 af1 = *(const float4*)&As[buf][kk][(ty << 3) + 4];
            ulonglong2 q0 = *(const ulonglong2*)&Ws[buf][kk][tx << 2];
            ulonglong2 q1 = *(const ulonglong2*)&Ws[buf][kk][64 + (tx << 2)];
            float av[8] = {af0.x, af0.y, af0.z, af0.w, af1.x, af1.y, af1.z, af1.w};
            #pragma unroll
            for (int i = 0; i < 8; ++i) {
                u64 ap = pk2(av[i], av[i]);
                acc[i][0] = fma2(ap, q0.x, acc[i][0]);
                acc[i][1] = fma2(ap, q0.y, acc[i][1]);
                acc[i][2] = fma2(ap, q1.x, acc[i][2]);
                acc[i][3] = fma2(ap, q1.y, acc[i][3]);
            }
        }
    }

    float* Cp = g_com4[blockIdx.z];
    #pragma unroll
    for (int i = 0; i < 8; ++i) {
        int row = m0 + (ty << 3) + i;
        *(ulonglong2*)&Cp[(size_t)row * 512 + n0 + (tx << 2)] =
            make_ulonglong2(acc[i][0], acc[i][1]);
        *(ulonglong2*)&Cp[(size_t)row * 512 + n0 + 64 + (tx << 2)] =
            make_ulonglong2(acc[i][2], acc[i][3]);
    }
}

// ---------------------------------------------------------------------------
// Quantum circuit: 1 CTA per batch row, state (4096 complex, AoS u64) in SMEM.
// Wire w <-> bit (11 - w).  Swizzle a(i) = i ^ ((i>>4) & 0xF).
// ---------------------------------------------------------------------------
__device__ __forceinline__ int swz(int i) { return i ^ ((i >> 4) & 0xF); }

// Packed complex 2x2 gate on pairs over local bit LB.
// cf = 8 splatted u64 coefficients; negation for the imag part is folded in:
//   c[2e]   = (m.x, m.x)        (e = matrix entry 00,01,10,11)
//   c[2e+1] = (-m.y, m.y)
// new = c0*A + c1*swap(A) + c2*B + c3*swap(B)   (per output half)
template<int LB>
__device__ __forceinline__ void rot2(u64* v, const u64* __restrict__ cf)
{
    u64 c0 = cf[0], c1 = cf[1], c2 = cf[2], c3 = cf[3];
    u64 c4 = cf[4], c5 = cf[5], c6 = cf[6], c7 = cf[7];
    #pragma unroll
    for (int p = 0; p < 8; ++p) {
        int k0 = ((p >> LB) << (LB + 1)) | (p & ((1 << LB) - 1));
        int k1 = k0 | (1 << LB);
        u64 A = v[k0], B = v[k1];
        u64 As_ = hswap(A), Bs = hswap(B);
        v[k0] = fma2(c0, A, fma2(c1, As_, fma2(c2, B, mul2(c3, Bs))));
        v[k1] = fma2(c4, A, fma2(c5, As_, fma2(c6, B, mul2(c7, Bs))));
    }
}

// Unscaled Hadamard butterfly (scale folded into final reduction).
template<int LB>
__device__ __forceinline__ void h2(u64* v, u64 neg1)
{
    #pragma unroll
    for (int p = 0; p < 8; ++p) {
        int k0 = ((p >> LB) << (LB + 1)) | (p & ((1 << LB) - 1));
        int k1 = k0 | (1 << LB);
        u64 A = v[k0], B = v[k1];
        v[k0] = add2(A, B);
        v[k1] = fma2(neg1, B, A);
    }
}

// Net gather index of the 12-CNOT chain with range R (GF(2)-linear).
template<int R>
__device__ __forceinline__ int cnotG(int i)
{
    #pragma unroll
    for (int w = 11; w >= 0; --w) {
        int pc = 11 - w;
        int pt = 11 - ((w + R) % 12);
        i ^= ((i >> pc) & 1) << pt;
    }
    return i;
}

__global__ __launch_bounds__(256, 3)
void circuit_kernel(const float* __restrict__ x,    // (1024, 2048) img angles
                    const float* __restrict__ bias, // (512,)
                    const float* __restrict__ qp,   // (2, 12, 3)
                    float* __restrict__ out)        // (1024,)
{
    __shared__ u64 st[4096];             // 32 KB state (packed complex)
    __shared__ u64 cf2[2][12][8];        // splatted gate coefficients
    __shared__ float red[8];

    const int t = threadIdx.x;
    const int b = blockIdx.x;
    const float* img = x + (size_t)b * 2048;
    const size_t crow = (size_t)b * 512;

    // --- Rot matrices, splatted: Rot = RZ(omega) RY(theta) RZ(phi) ---
    if (t < 24) {
        int l = t / 12, w = t % 12;
        float phi = qp[(l * 12 + w) * 3 + 0];
        float th  = qp[(l * 12 + w) * 3 + 1];
        float om  = qp[(l * 12 + w) * 3 + 2];
        float sh, ch;  sincosf(0.5f * th, &sh, &ch);
        float sa, ca;  sincosf(0.5f * (phi + om), &sa, &ca);
        float sb, cb;  sincosf(0.5f * (phi - om), &sb, &cb);
        u64* c = cf2[l][w];
        // m00 = (ch*ca, -ch*sa)
        c[0] = pk2( ch * ca,  ch * ca);
        c[1] = pk2( ch * sa, -ch * sa);
        // m01 = (-sh*cb, -sh*sb)
        c[2] = pk2(-sh * cb, -sh * cb);
        c[3] = pk2( sh * sb, -sh * sb);
        // m10 = (sh*cb, -sh*sb)
        c[4] = pk2( sh * cb,  sh * cb);
        c[5] = pk2( sh * sb, -sh * sb);
        // m11 = (ch*ca, ch*sa)
        c[6] = pk2( ch * ca,  ch * ca);
        c[7] = pk2(-ch * sa,  ch * sa);
    }
    __syncthreads();

    const u64 neg1 = pk2(-1.f, -1.f);
    u64 v[16];

    // ===== Pass 1 (nibble A: bits 0-3 local) : analytic FRQI(com), L0 Rots 11..8
    #pragma unroll
    for (int k = 0; k < 16; ++k) {
        int i = (t << 4) | k;
        if (i & 3) {
            v[k] = 0ull;
        } else {
            int j = (i >> 2) & 511;
            int aidx = __brev((unsigned)j) >> 23;
            float comv = bias[aidx];
            #pragma unroll
            for (int s = 0; s < SPLITK; ++s) comv += g_com4[s][crow + aidx];
            float sn, cs; __sincosf(0.5f * comv, &sn, &cs);
            float amp = ((i >> 11) & 1) ? sn : cs;
            v[k] = pk2(amp * 0.04419417382415922f, 0.f);  // 1/sqrt(512)
        }
    }
    rot2<0>(v, cf2[0][11]); rot2<1>(v, cf2[0][10]);
    rot2<2>(v, cf2[0][9]);  rot2<3>(v, cf2[0][8]);
    #pragma unroll
    for (int k = 0; k < 16; ++k) st[swz((t << 4) | k)] = v[k];
    __syncthreads();

    // ===== Pass 2 (B: bits 4-7) : L0 Rots 7..4
    #pragma unroll
    for (int k = 0; k < 16; ++k) v[k] = st[swz(((t >> 4) << 8) | (k << 4) | (t & 15))];
    rot2<0>(v, cf2[0][7]); rot2<1>(v, cf2[0][6]);
    rot2<2>(v, cf2[0][5]); rot2<3>(v, cf2[0][4]);
    #pragma unroll
    for (int k = 0; k < 16; ++k) st[swz(((t >> 4) << 8) | (k << 4) | (t & 15))] = v[k];
    __syncthreads();

    // ===== Pass 3 (C: bits 8-11) : L0 Rots 3..0
    #pragma unroll
    for (int k = 0; k < 16; ++k) v[k] = st[swz((k << 8) | t)];
    rot2<0>(v, cf2[0][3]); rot2<1>(v, cf2[0][2]);
    rot2<2>(v, cf2[0][1]); rot2<3>(v, cf2[0][0]);
    #pragma unroll
    for (int k = 0; k < 16; ++k) st[swz((k << 8) | t)] = v[k];
    __syncthreads();

    // ===== Pass 4 (A) : CNOT r=1 folded gather, L1 Rots 11..8
    {
        int base = cnotG<1>(t << 4);
        int m0 = cnotG<1>(1), m1 = cnotG<1>(2), m2 = cnotG<1>(4), m3 = cnotG<1>(8);
        #pragma unroll
        for (int k = 0; k < 16; ++k) {
            int gi = base ^ ((k & 1) ? m0 : 0) ^ ((k & 2) ? m1 : 0)
                          ^ ((k & 4) ? m2 : 0) ^ ((k & 8) ? m3 : 0);
            v[k] = st[swz(gi)];
        }
    }
    __syncthreads();
    rot2<0>(v, cf2[1][11]); rot2<1>(v, cf2[1][10]);
    rot2<2>(v, cf2[1][9]);  rot2<3>(v, cf2[1][8]);
    #pragma unroll
    for (int k = 0; k < 16; ++k) st[swz((t << 4) | k)] = v[k];
    __syncthreads();

    // ===== Pass 5 (B) : L1 Rots 7..4
    #pragma unroll
    for (int k = 0; k < 16; ++k) v[k] = st[swz(((t >> 4) << 8) | (k << 4) | (t & 15))];
    rot2<0>(v, cf2[1][7]); rot2<1>(v, cf2[1][6]);
    rot2<2>(v, cf2[1][5]); rot2<3>(v, cf2[1][4]);
    #pragma unroll
    for (int k = 0; k < 16; ++k) st[swz(((t >> 4) << 8) | (k << 4) | (t & 15))] = v[k];
    __syncthreads();

    // ===== Pass 6 (C) : L1 Rots 3..0
    #pragma unroll
    for (int k = 0; k < 16; ++k) v[k] = st[swz((k << 8) | t)];
    rot2<0>(v, cf2[1][3]); rot2<1>(v, cf2[1][2]);
    rot2<2>(v, cf2[1][1]); rot2<3>(v, cf2[1][0]);
    #pragma unroll
    for (int k = 0; k < 16; ++k) st[swz((k << 8) | t)] = v[k];
    __syncthreads();

    // ===== Pass 7 (A) : CNOT r=2 folded gather, H on bits 0-3 (unscaled)
    {
        int base = cnotG<2>(t << 4);
        int m0 = cnotG<2>(1), m1 = cnotG<2>(2), m2 = cnotG<2>(4), m3 = cnotG<2>(8);
        #pragma unroll
        for (int k = 0; k < 16; ++k) {
            int gi = base ^ ((k & 1) ? m0 : 0) ^ ((k & 2) ? m1 : 0)
                          ^ ((k & 4) ? m2 : 0) ^ ((k & 8) ? m3 : 0);
            v[k] = st[swz(gi)];
        }
    }
    __syncthreads();
    h2<0>(v, neg1); h2<1>(v, neg1); h2<2>(v, neg1); h2<3>(v, neg1);
    #pragma unroll
    for (int k = 0; k < 16; ++k) st[swz((t << 4) | k)] = v[k];
    __syncthreads();

    // ===== Pass 8 (B) : H on bits 4-7 (unscaled)
    #pragma unroll
    for (int k = 0; k < 16; ++k) v[k] = st[swz(((t >> 4) << 8) | (k << 4) | (t & 15))];
    h2<0>(v, neg1); h2<1>(v, neg1); h2<2>(v, neg1); h2<3>(v, neg1);
    #pragma unroll
    for (int k = 0; k < 16; ++k) st[swz(((t >> 4) << 8) | (k << 4) | (t & 15))] = v[k];
    __syncthreads();

    // ===== Pass 9 (C) : H bits 8-10 (unscaled), UC-RY(img) on wire 0, measure
    #pragma unroll
    for (int k = 0; k < 16; ++k) v[k] = st[swz((k << 8) | t)];
    h2<0>(v, neg1); h2<1>(v, neg1); h2<2>(v, neg1);

    #pragma unroll
    for (int k0 = 0; k0 < 8; ++k0) {
        int i0 = (k0 << 8) | t;
        int aidx = __brev((unsigned)i0) >> 21;
        float sn, cs; __sincosf(0.5f * img[aidx], &sn, &cs);
        u64 A = v[k0], B = v[k0 + 8];
        u64 cs2 = pk2(cs, cs), sn2 = pk2(sn, sn), sn2n = pk2(-sn, -sn);
        v[k0]     = fma2(cs2, A, mul2(sn2n, B));
        v[k0 + 8] = fma2(sn2, A, mul2(cs2, B));
    }

    u64 accN = 0ull, accP = 0ull;
    #pragma unroll
    for (int k = 0; k < 8; ++k)  accN = fma2(v[k], v[k], accN);
    #pragma unroll
    for (int k = 8; k < 16; ++k) accP = fma2(v[k], v[k], accP);
    float pl, ph, nl, nh;
    unpk2(pl, ph, accP); unpk2(nl, nh, accN);
    float acc = (pl + ph) - (nl + nh);

    #pragma unroll
    for (int o = 16; o; o >>= 1) acc += __shfl_xor_sync(0xffffffffu, acc, o);
    if ((t & 31) == 0) red[t >> 5] = acc;
    __syncthreads();
    if (t == 0) {
        float s = 0.f;
        #pragma unroll
        for (int w = 0; w < 8; ++w) s += red[w];
        out[b] = s * (1.0f / 2048.0f);   // fold (1/sqrt(2))^11 (squared) scale
    }
}

// ---------------------------------------------------------------------------
extern "C" void kernel_launch(void* const* d_in, const int* in_sizes, int n_in,
                              void* d_out, int out_size)
{
    const float* x  = (const float*)d_in[0];   // (1024, 2, 32, 32) -> (1024, 2048)
    const float* Wm = (const float*)d_in[1];   // (512, 2048)
    const float* bb = (const float*)d_in[2];   // (512,)
    const float* qp = (const float*)d_in[3];   // (2, 12, 3)
    float* out = (float*)d_out;                // (1024,)

    dim3 gemm_grid(512 / 128, 1024 / 128, SPLITK);   // (4, 8, 8) = 256 CTAs
    gemm_v2<<<gemm_grid, 256>>>(x, Wm);
    circuit_kernel<<<1024, 256>>>(x, bb, qp, out);
}